// round 11
// baseline (speedup 1.0000x reference)
#include <cuda_runtime.h>

#define N_NODES 100000
#define N_REL 3
#define E_REL 800000
#define E_DEC 500000
#define D 64
#define M_BUCKETS (N_REL * N_NODES)          // 300000
#define E_TOT (N_REL * E_REL)                // 2400000
#define SCAN_BS 512
#define N_SCAN_BLK ((M_BUCKETS + SCAN_BS - 1) / SCAN_BS)  // 586

typedef unsigned long long ull;

// ---- scratch (__device__ globals; no allocs allowed) ----
__device__ float g_ns[M_BUCKETS];
__device__ float g_nd[M_BUCKETS];
__device__ int   g_odeg[M_BUCKETS];
__device__ int   g_ideg[M_BUCKETS];
__device__ int   g_off[M_BUCKETS + 1];
__device__ int   g_cur[M_BUCKETS];
__device__ int   g_bsum[1024];
__device__ ull   g_epack[E_TOT];                      // (coef<<32)|src, 19.2 MB
__device__ float g_t[(size_t)N_REL * N_NODES * D];    // 76.8 MB (aggregated rows)
__device__ float g_h1[(size_t)N_NODES * D];           // 25.6 MB
__device__ float g_h2[(size_t)N_NODES * D];           // 25.6 MB

__global__ void k_zero_deg() {
    int i = blockIdx.x * blockDim.x + threadIdx.x;
    if (i < M_BUCKETS) { g_odeg[i] = 0; g_ideg[i] = 0; }
}

__global__ void k_degree(const int* __restrict__ edges) {
    int t = blockIdx.x * blockDim.x + threadIdx.x;
    if (t >= E_TOT) return;
    int r = t / E_REL;
    int e = t - r * E_REL;
    int s = edges[(r * 2 + 0) * E_REL + e];
    int d = edges[(r * 2 + 1) * E_REL + e];
    atomicAdd(&g_odeg[r * N_NODES + s], 1);
    atomicAdd(&g_ideg[r * N_NODES + d], 1);
}

__global__ void k_norm() {
    int i = blockIdx.x * blockDim.x + threadIdx.x;
    if (i < M_BUCKETS) {
        g_ns[i] = rsqrtf((float)max(g_odeg[i], 1));
        g_nd[i] = rsqrtf((float)max(g_ideg[i], 1));
    }
}

// ---- 3-pass exclusive prefix scan of g_ideg -> g_off ----
__global__ void k_scan_a() {
    int i = blockIdx.x * SCAN_BS + threadIdx.x;
    int v = (i < M_BUCKETS) ? g_ideg[i] : 0;
    int lane = threadIdx.x & 31, wid = threadIdx.x >> 5;
    int inc = v;
#pragma unroll
    for (int o = 1; o < 32; o <<= 1) {
        int t = __shfl_up_sync(0xffffffffu, inc, o);
        if (lane >= o) inc += t;
    }
    __shared__ int wsum[SCAN_BS / 32];
    if (lane == 31) wsum[wid] = inc;
    __syncthreads();
    if (wid == 0) {
        int s = (lane < SCAN_BS / 32) ? wsum[lane] : 0;
#pragma unroll
        for (int o = 1; o < SCAN_BS / 32; o <<= 1) {
            int t = __shfl_up_sync(0xffffffffu, s, o);
            if (lane >= o) s += t;
        }
        if (lane < SCAN_BS / 32) wsum[lane] = s;
    }
    __syncthreads();
    int excl = inc - v + (wid > 0 ? wsum[wid - 1] : 0);
    if (i < M_BUCKETS) g_off[i] = excl;
    if (threadIdx.x == SCAN_BS - 1) g_bsum[blockIdx.x] = excl + v;
}

__global__ void k_scan_b() {
    int tid = threadIdx.x;                  // 1024 threads
    int v = (tid < N_SCAN_BLK) ? g_bsum[tid] : 0;
    int lane = tid & 31, wid = tid >> 5;
    int inc = v;
#pragma unroll
    for (int o = 1; o < 32; o <<= 1) {
        int t = __shfl_up_sync(0xffffffffu, inc, o);
        if (lane >= o) inc += t;
    }
    __shared__ int wsum[32];
    if (lane == 31) wsum[wid] = inc;
    __syncthreads();
    if (wid == 0) {
        int s = (lane < 32) ? wsum[lane] : 0;
#pragma unroll
        for (int o = 1; o < 32; o <<= 1) {
            int t = __shfl_up_sync(0xffffffffu, s, o);
            if (lane >= o) s += t;
        }
        wsum[lane] = s;
    }
    __syncthreads();
    int excl = inc - v + (wid > 0 ? wsum[wid - 1] : 0);
    if (tid < N_SCAN_BLK) g_bsum[tid] = excl;
}

__global__ void k_scan_c() {
    int i = blockIdx.x * blockDim.x + threadIdx.x;
    if (i < M_BUCKETS) {
        int off = g_off[i] + g_bsum[i / SCAN_BS];
        g_off[i] = off;
        g_cur[i] = off;
    }
    if (i == 0) g_off[M_BUCKETS] = E_TOT;
}

__global__ void k_fill(const int* __restrict__ edges) {
    int t = blockIdx.x * blockDim.x + threadIdx.x;
    if (t >= E_TOT) return;
    int r = t / E_REL;
    int e = t - r * E_REL;
    int s = edges[(r * 2 + 0) * E_REL + e];
    int d = edges[(r * 2 + 1) * E_REL + e];
    float c = g_ns[r * N_NODES + s];
    int pos = atomicAdd(&g_cur[r * N_NODES + d], 1);
    g_epack[pos] = ((ull)__float_as_uint(c) << 32) | (unsigned)s;
}

// ---- CSR pull aggregation from `feat` (L2-hot). No atomics.
// Warp per dst; 32 lanes cover the 64-float row (float2 each).
// Batch-load 32 packed (src,coef) records lane-parallel, broadcast via shfl,
// issue gathers in groups of 8 independent LDG.64 for MLP.
// Output: g_t[(r,d)] = nd_r[d] * sum_e coef_e * feat[src_e]
__global__ void __launch_bounds__(256) k_agg(const float* __restrict__ feat) {
    int d = blockIdx.x * 8 + (threadIdx.x >> 5);   // grid exact: 12500*8=100000
    int lane = threadIdx.x & 31;
    int col = lane * 2;

#pragma unroll
    for (int r = 0; r < N_REL; r++) {
        int m = r * N_NODES + d;
        int start = g_off[m], end = g_off[m + 1];
        float ax = 0.f, ay = 0.f;

        for (int base = start; base < end; base += 32) {
            int cnt = min(32, end - base);
            ull pk = 0;
            if (base + lane < end) pk = g_epack[base + lane];
            int   sidx = (int)(unsigned)(pk & 0xffffffffu);
            float cef  = __uint_as_float((unsigned)(pk >> 32));

            for (int j = 0; j < cnt; j += 8) {
                float vx[8], vy[8], cc[8];
#pragma unroll
                for (int u = 0; u < 8; u++) {
                    int k = j + u;
                    if (k < cnt) {          // warp-uniform condition
                        int ss = __shfl_sync(0xffffffffu, sidx, k);
                        cc[u]  = __shfl_sync(0xffffffffu, cef, k);
                        float2 v = *reinterpret_cast<const float2*>(
                            feat + (size_t)ss * D + col);
                        vx[u] = v.x; vy[u] = v.y;
                    } else { cc[u] = 0.f; vx[u] = 0.f; vy[u] = 0.f; }
                }
#pragma unroll
                for (int u = 0; u < 8; u++) {
                    ax += vx[u] * cc[u];
                    ay += vy[u] * cc[u];
                }
            }
        }
        float ndv = g_nd[m];
        *reinterpret_cast<float2*>(g_t + (size_t)m * D + col) =
            make_float2(ax * ndv, ay * ndv);
    }
}

// ---- Combine MLP: out[n] = (relu?)( sum_r g_t[(r,n)] @ W_r + sum_r b_r )
// Thread = 2 nodes x 32 outputs: each W LDS.64 feeds 2 FFMA2 (halved LDS).
__global__ void __launch_bounds__(256) k_mlp(float* __restrict__ out,
                                             const float* __restrict__ W,
                                             const float* __restrict__ b,
                                             int do_relu) {
    __shared__ float sW[D * D];   // 16 KB (per relation)
    __shared__ float sb[D];
    if (threadIdx.x < D)
        sb[threadIdx.x] = b[threadIdx.x] + b[D + threadIdx.x] + b[2 * D + threadIdx.x];

    int pair = threadIdx.x >> 1;          // 0..127
    int jh = (threadIdx.x & 1) * 32;      // output col offset
    int n0 = blockIdx.x * 256 + pair * 2;
    int n1 = n0 + 1;
    bool ok0 = n0 < N_NODES, ok1 = n1 < N_NODES;

    ull acc[32];                          // [0..15]=node0, [16..31]=node1
#pragma unroll
    for (int i = 0; i < 32; i++) acc[i] = 0ull;

    for (int r = 0; r < N_REL; r++) {
        __syncthreads();
        for (int i = threadIdx.x; i < D * D / 4; i += 256)
            reinterpret_cast<float4*>(sW)[i] =
                reinterpret_cast<const float4*>(W + r * D * D)[i];
        __syncthreads();

        const float4* t0 = reinterpret_cast<const float4*>(
            g_t + ((size_t)r * N_NODES + n0) * D);
        const float4* t1 = reinterpret_cast<const float4*>(
            g_t + ((size_t)r * N_NODES + n1) * D);

#pragma unroll 4
        for (int k4 = 0; k4 < D / 4; k4++) {
            float4 a0 = ok0 ? t0[k4] : make_float4(0, 0, 0, 0);
            float4 a1 = ok1 ? t1[k4] : make_float4(0, 0, 0, 0);
            float a0v[4] = {a0.x, a0.y, a0.z, a0.w};
            float a1v[4] = {a1.x, a1.y, a1.z, a1.w};
#pragma unroll
            for (int kk = 0; kk < 4; kk++) {
                ull b0, b1;
                asm("mov.b64 %0, {%1, %1};" : "=l"(b0) : "f"(a0v[kk]));
                asm("mov.b64 %0, {%1, %1};" : "=l"(b1) : "f"(a1v[kk]));
                const ull* wrow = reinterpret_cast<const ull*>(
                    sW + (k4 * 4 + kk) * D + jh);
#pragma unroll
                for (int jp = 0; jp < 16; jp++) {
                    ull w = wrow[jp];
                    asm("fma.rn.f32x2 %0, %1, %2, %0;" : "+l"(acc[jp]) : "l"(b0), "l"(w));
                    asm("fma.rn.f32x2 %0, %1, %2, %0;" : "+l"(acc[16 + jp]) : "l"(b1), "l"(w));
                }
            }
        }
    }

#pragma unroll
    for (int node = 0; node < 2; node++) {
        int n = node ? n1 : n0;
        if (n >= N_NODES) continue;
        float4* orow = reinterpret_cast<float4*>(out + (size_t)n * D + jh);
#pragma unroll
        for (int q = 0; q < 16; q += 2) {   // all 16 ull accs = 32 floats
            float v0, v1, v2, v3;
            asm("mov.b64 {%0, %1}, %2;" : "=f"(v0), "=f"(v1) : "l"(acc[node * 16 + q]));
            asm("mov.b64 {%0, %1}, %2;" : "=f"(v2), "=f"(v3) : "l"(acc[node * 16 + q + 1]));
            int j = jh + q * 2;
            v0 += sb[j + 0]; v1 += sb[j + 1]; v2 += sb[j + 2]; v3 += sb[j + 3];
            if (do_relu) {
                v0 = fmaxf(v0, 0.f); v1 = fmaxf(v1, 0.f);
                v2 = fmaxf(v2, 0.f); v3 = fmaxf(v3, 0.f);
            }
            orow[q / 2] = make_float4(v0, v1, v2, v3);
        }
    }
}

// ---- Edge scorer: one warp per dec edge ----
__global__ void __launch_bounds__(256) k_decoder(const int* __restrict__ dec,
                                                 const float* __restrict__ Wp,
                                                 const float* __restrict__ bp,
                                                 float* __restrict__ out) {
    __shared__ float sW[2 * D * N_REL];
    __shared__ float sb[N_REL];
    for (int i = threadIdx.x; i < 2 * D * N_REL; i += blockDim.x) sW[i] = Wp[i];
    if (threadIdx.x < N_REL) sb[threadIdx.x] = bp[threadIdx.x];
    __syncthreads();

    int e = blockIdx.x * 8 + (threadIdx.x >> 5);
    if (e >= E_DEC) return;
    int lane = threadIdx.x & 31;
    int s = dec[e];
    int d = dec[E_DEC + e];
    float2 a  = *reinterpret_cast<const float2*>(g_h2 + (size_t)s * D + lane * 2);
    float2 bb = *reinterpret_cast<const float2*>(g_h2 + (size_t)d * D + lane * 2);

    int j0 = lane * 2;
    float p0, p1, p2;
    p0 = a.x  * sW[(j0 + 0) * 3 + 0] + a.y  * sW[(j0 + 1) * 3 + 0]
       + bb.x * sW[(D + j0 + 0) * 3 + 0] + bb.y * sW[(D + j0 + 1) * 3 + 0];
    p1 = a.x  * sW[(j0 + 0) * 3 + 1] + a.y  * sW[(j0 + 1) * 3 + 1]
       + bb.x * sW[(D + j0 + 0) * 3 + 1] + bb.y * sW[(D + j0 + 1) * 3 + 1];
    p2 = a.x  * sW[(j0 + 0) * 3 + 2] + a.y  * sW[(j0 + 1) * 3 + 2]
       + bb.x * sW[(D + j0 + 0) * 3 + 2] + bb.y * sW[(D + j0 + 1) * 3 + 2];

#pragma unroll
    for (int off = 16; off; off >>= 1) {
        p0 += __shfl_xor_sync(0xffffffffu, p0, off);
        p1 += __shfl_xor_sync(0xffffffffu, p1, off);
        p2 += __shfl_xor_sync(0xffffffffu, p2, off);
    }
    if (lane == 0) {
        out[(size_t)e * 3 + 0] = p0 + sb[0];
        out[(size_t)e * 3 + 1] = p1 + sb[1];
        out[(size_t)e * 3 + 2] = p2 + sb[2];
    }
}

extern "C" void kernel_launch(void* const* d_in, const int* in_sizes, int n_in,
                              void* d_out, int out_size) {
    (void)in_sizes; (void)n_in; (void)out_size;
    const float* x    = (const float*)d_in[0];
    const int*   edges= (const int*)d_in[1];
    const int*   dec  = (const int*)d_in[2];
    const float* W1   = (const float*)d_in[3];
    const float* b1   = (const float*)d_in[4];
    const float* W2   = (const float*)d_in[5];
    const float* b2   = (const float*)d_in[6];
    const float* Wp   = (const float*)d_in[7];
    const float* bp   = (const float*)d_in[8];
    float* out = (float*)d_out;

    void *p_h1 = nullptr, *p_h2 = nullptr;
    cudaGetSymbolAddress(&p_h1, g_h1);
    cudaGetSymbolAddress(&p_h2, g_h2);
    float* h1 = (float*)p_h1;
    float* h2 = (float*)p_h2;

    const int TB = 256;
    // degrees + norms (edges identical for both layers)
    k_zero_deg<<<(M_BUCKETS + TB - 1) / TB, TB>>>();
    k_degree<<<(E_TOT + TB - 1) / TB, TB>>>(edges);
    k_norm<<<(M_BUCKETS + TB - 1) / TB, TB>>>();

    // CSR build with packed (src, ns[src]) records; reused by both layers
    k_scan_a<<<N_SCAN_BLK, SCAN_BS>>>();
    k_scan_b<<<1, 1024>>>();
    k_scan_c<<<(M_BUCKETS + TB - 1) / TB, TB>>>();
    k_fill<<<(E_TOT + TB - 1) / TB, TB>>>(edges);

    int agrid = N_NODES / 8;                 // 12500, exact
    int mgrid = (N_NODES + 255) / 256;       // 391

    // layer 1: t_r[d] = nd*sum(ns*x[src]) ; h1 = relu(sum_r t_r @ W1_r + sum b1)
    k_agg<<<agrid, TB>>>(x);
    k_mlp<<<mgrid, TB>>>(h1, W1, b1, 1);

    // layer 2
    k_agg<<<agrid, TB>>>(h1);
    k_mlp<<<mgrid, TB>>>(h2, W2, b2, 0);

    // decoder
    k_decoder<<<(E_DEC + 7) / 8, TB>>>(dec, Wp, bp, out);
}

// round 12
// speedup vs baseline: 1.0668x; 1.0668x over previous
#include <cuda_runtime.h>

#define N_NODES 100000
#define N_REL 3
#define E_REL 800000
#define E_DEC 500000
#define D 64
#define M_BUCKETS (N_REL * N_NODES)          // 300000
#define E_TOT (N_REL * E_REL)                // 2400000
#define SCAN_BS 512
#define N_SCAN_BLK ((M_BUCKETS + SCAN_BS - 1) / SCAN_BS)  // 586

typedef unsigned long long ull;

// ---- scratch (__device__ globals; no allocs allowed) ----
__device__ float g_ns[M_BUCKETS];
__device__ float g_nd[M_BUCKETS];
__device__ int   g_odeg[M_BUCKETS];
__device__ int   g_ideg[M_BUCKETS];
__device__ int   g_off[M_BUCKETS + 1];
__device__ int   g_cur[M_BUCKETS];
__device__ int   g_bsum[1024];
__device__ ull   g_epack[E_TOT];                      // (coef<<32)|src, 19.2 MB
__device__ float g_t[(size_t)N_REL * N_NODES * D];    // 76.8 MB (aggregated rows)
__device__ float g_h1[(size_t)N_NODES * D];           // 25.6 MB
__device__ float g_h2[(size_t)N_NODES * D];           // 25.6 MB

__global__ void k_zero_deg() {
    int i = blockIdx.x * blockDim.x + threadIdx.x;
    if (i < M_BUCKETS) { g_odeg[i] = 0; g_ideg[i] = 0; }
}

__global__ void k_degree(const int* __restrict__ edges) {
    int t = blockIdx.x * blockDim.x + threadIdx.x;
    if (t >= E_TOT) return;
    int r = t / E_REL;
    int e = t - r * E_REL;
    int s = edges[(r * 2 + 0) * E_REL + e];
    int d = edges[(r * 2 + 1) * E_REL + e];
    atomicAdd(&g_odeg[r * N_NODES + s], 1);
    atomicAdd(&g_ideg[r * N_NODES + d], 1);
}

__global__ void k_norm() {
    int i = blockIdx.x * blockDim.x + threadIdx.x;
    if (i < M_BUCKETS) {
        g_ns[i] = rsqrtf((float)max(g_odeg[i], 1));
        g_nd[i] = rsqrtf((float)max(g_ideg[i], 1));
    }
}

// ---- 3-pass exclusive prefix scan of g_ideg -> g_off ----
__global__ void k_scan_a() {
    int i = blockIdx.x * SCAN_BS + threadIdx.x;
    int v = (i < M_BUCKETS) ? g_ideg[i] : 0;
    int lane = threadIdx.x & 31, wid = threadIdx.x >> 5;
    int inc = v;
#pragma unroll
    for (int o = 1; o < 32; o <<= 1) {
        int t = __shfl_up_sync(0xffffffffu, inc, o);
        if (lane >= o) inc += t;
    }
    __shared__ int wsum[SCAN_BS / 32];
    if (lane == 31) wsum[wid] = inc;
    __syncthreads();
    if (wid == 0) {
        int s = (lane < SCAN_BS / 32) ? wsum[lane] : 0;
#pragma unroll
        for (int o = 1; o < SCAN_BS / 32; o <<= 1) {
            int t = __shfl_up_sync(0xffffffffu, s, o);
            if (lane >= o) s += t;
        }
        if (lane < SCAN_BS / 32) wsum[lane] = s;
    }
    __syncthreads();
    int excl = inc - v + (wid > 0 ? wsum[wid - 1] : 0);
    if (i < M_BUCKETS) g_off[i] = excl;
    if (threadIdx.x == SCAN_BS - 1) g_bsum[blockIdx.x] = excl + v;
}

__global__ void k_scan_b() {
    int tid = threadIdx.x;                  // 1024 threads
    int v = (tid < N_SCAN_BLK) ? g_bsum[tid] : 0;
    int lane = tid & 31, wid = tid >> 5;
    int inc = v;
#pragma unroll
    for (int o = 1; o < 32; o <<= 1) {
        int t = __shfl_up_sync(0xffffffffu, inc, o);
        if (lane >= o) inc += t;
    }
    __shared__ int wsum[32];
    if (lane == 31) wsum[wid] = inc;
    __syncthreads();
    if (wid == 0) {
        int s = (lane < 32) ? wsum[lane] : 0;
#pragma unroll
        for (int o = 1; o < 32; o <<= 1) {
            int t = __shfl_up_sync(0xffffffffu, s, o);
            if (lane >= o) s += t;
        }
        wsum[lane] = s;
    }
    __syncthreads();
    int excl = inc - v + (wid > 0 ? wsum[wid - 1] : 0);
    if (tid < N_SCAN_BLK) g_bsum[tid] = excl;
}

__global__ void k_scan_c() {
    int i = blockIdx.x * blockDim.x + threadIdx.x;
    if (i < M_BUCKETS) {
        int off = g_off[i] + g_bsum[i / SCAN_BS];
        g_off[i] = off;
        g_cur[i] = off;
    }
    if (i == 0) g_off[M_BUCKETS] = E_TOT;
}

__global__ void k_fill(const int* __restrict__ edges) {
    int t = blockIdx.x * blockDim.x + threadIdx.x;
    if (t >= E_TOT) return;
    int r = t / E_REL;
    int e = t - r * E_REL;
    int s = edges[(r * 2 + 0) * E_REL + e];
    int d = edges[(r * 2 + 1) * E_REL + e];
    float c = g_ns[r * N_NODES + s];
    int pos = atomicAdd(&g_cur[r * N_NODES + d], 1);
    g_epack[pos] = ((ull)__float_as_uint(c) << 32) | (unsigned)s;
}

// ---- CSR pull aggregation from `feat` (L2-hot). No atomics. (unchanged vs R11)
// Output: g_t[(r,d)] = nd_r[d] * sum_e coef_e * feat[src_e]
__global__ void __launch_bounds__(256) k_agg(const float* __restrict__ feat) {
    int d = blockIdx.x * 8 + (threadIdx.x >> 5);   // grid exact: 12500*8=100000
    int lane = threadIdx.x & 31;
    int col = lane * 2;

#pragma unroll
    for (int r = 0; r < N_REL; r++) {
        int m = r * N_NODES + d;
        int start = g_off[m], end = g_off[m + 1];
        float ax = 0.f, ay = 0.f;

        for (int base = start; base < end; base += 32) {
            int cnt = min(32, end - base);
            ull pk = 0;
            if (base + lane < end) pk = g_epack[base + lane];
            int   sidx = (int)(unsigned)(pk & 0xffffffffu);
            float cef  = __uint_as_float((unsigned)(pk >> 32));

            for (int j = 0; j < cnt; j += 8) {
                float vx[8], vy[8], cc[8];
#pragma unroll
                for (int u = 0; u < 8; u++) {
                    int k = j + u;
                    if (k < cnt) {          // warp-uniform condition
                        int ss = __shfl_sync(0xffffffffu, sidx, k);
                        cc[u]  = __shfl_sync(0xffffffffu, cef, k);
                        float2 v = *reinterpret_cast<const float2*>(
                            feat + (size_t)ss * D + col);
                        vx[u] = v.x; vy[u] = v.y;
                    } else { cc[u] = 0.f; vx[u] = 0.f; vy[u] = 0.f; }
                }
#pragma unroll
                for (int u = 0; u < 8; u++) {
                    ax += vx[u] * cc[u];
                    ay += vy[u] * cc[u];
                }
            }
        }
        float ndv = g_nd[m];
        *reinterpret_cast<float2*>(g_t + (size_t)m * D + col) =
            make_float2(ax * ndv, ay * ndv);
    }
}

// ---- Combine MLP (REVERTED to R4-style thread-per-node):
// out[n] = (relu?)( sum_r g_t[(r,n)] @ W_r + sum_r b_r )
// Each thread owns one node's full 64-float row; rows read ONCE; FFMA2 packed.
__global__ void __launch_bounds__(128) k_mlp(float* __restrict__ out,
                                             const float* __restrict__ W,
                                             const float* __restrict__ b,
                                             int do_relu) {
    __shared__ float sW[D * D];  // 16 KB, per relation
    __shared__ float sb[D];
    if (threadIdx.x < D)
        sb[threadIdx.x] = b[threadIdx.x] + b[D + threadIdx.x] + b[2 * D + threadIdx.x];
    int n = blockIdx.x * 128 + threadIdx.x;

    ull acc[D / 2];  // 32 packed f32x2 accumulators
#pragma unroll
    for (int i = 0; i < D / 2; i++) acc[i] = 0ull;

    for (int r = 0; r < N_REL; r++) {
        __syncthreads();
        for (int i = threadIdx.x; i < D * D / 4; i += 128)
            reinterpret_cast<float4*>(sW)[i] =
                reinterpret_cast<const float4*>(W + r * D * D)[i];
        __syncthreads();

        if (n < N_NODES) {
            const float4* arow = reinterpret_cast<const float4*>(
                g_t + ((size_t)r * N_NODES + n) * D);
#pragma unroll
            for (int i4 = 0; i4 < D / 4; i4++) {
                float4 a = arow[i4];
                float av[4] = {a.x, a.y, a.z, a.w};
#pragma unroll
                for (int k = 0; k < 4; k++) {
                    ull av2;
                    asm("mov.b64 %0, {%1, %1};" : "=l"(av2) : "f"(av[k]));
                    const ull* wrow = reinterpret_cast<const ull*>(
                        sW + (i4 * 4 + k) * D);
#pragma unroll
                    for (int jp = 0; jp < D / 2; jp++) {
                        asm("fma.rn.f32x2 %0, %1, %2, %0;"
                            : "+l"(acc[jp]) : "l"(av2), "l"(wrow[jp]));
                    }
                }
            }
        }
    }

    if (n < N_NODES) {
        float4* orow = reinterpret_cast<float4*>(out + (size_t)n * D);
#pragma unroll
        for (int q = 0; q < D / 4; q++) {
            float v0, v1, v2, v3;
            asm("mov.b64 {%0, %1}, %2;" : "=f"(v0), "=f"(v1) : "l"(acc[2 * q]));
            asm("mov.b64 {%0, %1}, %2;" : "=f"(v2), "=f"(v3) : "l"(acc[2 * q + 1]));
            int j = 4 * q;
            v0 += sb[j + 0]; v1 += sb[j + 1]; v2 += sb[j + 2]; v3 += sb[j + 3];
            if (do_relu) {
                v0 = fmaxf(v0, 0.f); v1 = fmaxf(v1, 0.f);
                v2 = fmaxf(v2, 0.f); v3 = fmaxf(v3, 0.f);
            }
            orow[q] = make_float4(v0, v1, v2, v3);
        }
    }
}

// ---- Edge scorer: one warp per dec edge ----
__global__ void __launch_bounds__(256) k_decoder(const int* __restrict__ dec,
                                                 const float* __restrict__ Wp,
                                                 const float* __restrict__ bp,
                                                 float* __restrict__ out) {
    __shared__ float sW[2 * D * N_REL];
    __shared__ float sb[N_REL];
    for (int i = threadIdx.x; i < 2 * D * N_REL; i += blockDim.x) sW[i] = Wp[i];
    if (threadIdx.x < N_REL) sb[threadIdx.x] = bp[threadIdx.x];
    __syncthreads();

    int e = blockIdx.x * 8 + (threadIdx.x >> 5);
    if (e >= E_DEC) return;
    int lane = threadIdx.x & 31;
    int s = dec[e];
    int d = dec[E_DEC + e];
    float2 a  = *reinterpret_cast<const float2*>(g_h2 + (size_t)s * D + lane * 2);
    float2 bb = *reinterpret_cast<const float2*>(g_h2 + (size_t)d * D + lane * 2);

    int j0 = lane * 2;
    float p0, p1, p2;
    p0 = a.x  * sW[(j0 + 0) * 3 + 0] + a.y  * sW[(j0 + 1) * 3 + 0]
       + bb.x * sW[(D + j0 + 0) * 3 + 0] + bb.y * sW[(D + j0 + 1) * 3 + 0];
    p1 = a.x  * sW[(j0 + 0) * 3 + 1] + a.y  * sW[(j0 + 1) * 3 + 1]
       + bb.x * sW[(D + j0 + 0) * 3 + 1] + bb.y * sW[(D + j0 + 1) * 3 + 1];
    p2 = a.x  * sW[(j0 + 0) * 3 + 2] + a.y  * sW[(j0 + 1) * 3 + 2]
       + bb.x * sW[(D + j0 + 0) * 3 + 2] + bb.y * sW[(D + j0 + 1) * 3 + 2];

#pragma unroll
    for (int off = 16; off; off >>= 1) {
        p0 += __shfl_xor_sync(0xffffffffu, p0, off);
        p1 += __shfl_xor_sync(0xffffffffu, p1, off);
        p2 += __shfl_xor_sync(0xffffffffu, p2, off);
    }
    if (lane == 0) {
        out[(size_t)e * 3 + 0] = p0 + sb[0];
        out[(size_t)e * 3 + 1] = p1 + sb[1];
        out[(size_t)e * 3 + 2] = p2 + sb[2];
    }
}

extern "C" void kernel_launch(void* const* d_in, const int* in_sizes, int n_in,
                              void* d_out, int out_size) {
    (void)in_sizes; (void)n_in; (void)out_size;
    const float* x    = (const float*)d_in[0];
    const int*   edges= (const int*)d_in[1];
    const int*   dec  = (const int*)d_in[2];
    const float* W1   = (const float*)d_in[3];
    const float* b1   = (const float*)d_in[4];
    const float* W2   = (const float*)d_in[5];
    const float* b2   = (const float*)d_in[6];
    const float* Wp   = (const float*)d_in[7];
    const float* bp   = (const float*)d_in[8];
    float* out = (float*)d_out;

    void *p_h1 = nullptr, *p_h2 = nullptr;
    cudaGetSymbolAddress(&p_h1, g_h1);
    cudaGetSymbolAddress(&p_h2, g_h2);
    float* h1 = (float*)p_h1;
    float* h2 = (float*)p_h2;

    const int TB = 256;
    // degrees + norms (edges identical for both layers)
    k_zero_deg<<<(M_BUCKETS + TB - 1) / TB, TB>>>();
    k_degree<<<(E_TOT + TB - 1) / TB, TB>>>(edges);
    k_norm<<<(M_BUCKETS + TB - 1) / TB, TB>>>();

    // CSR build with packed (src, ns[src]) records; reused by both layers
    k_scan_a<<<N_SCAN_BLK, SCAN_BS>>>();
    k_scan_b<<<1, 1024>>>();
    k_scan_c<<<(M_BUCKETS + TB - 1) / TB, TB>>>();
    k_fill<<<(E_TOT + TB - 1) / TB, TB>>>(edges);

    int agrid = N_NODES / 8;                 // 12500, exact
    int mgrid = (N_NODES + 127) / 128;       // 782

    // layer 1: t_r[d] = nd*sum(ns*x[src]) ; h1 = relu(sum_r t_r @ W1_r + sum b1)
    k_agg<<<agrid, TB>>>(x);
    k_mlp<<<mgrid, 128>>>(h1, W1, b1, 1);

    // layer 2
    k_agg<<<agrid, TB>>>(h1);
    k_mlp<<<mgrid, 128>>>(h2, W2, b2, 0);

    // decoder
    k_decoder<<<(E_DEC + 7) / 8, TB>>>(dec, Wp, bp, out);
}